// round 4
// baseline (speedup 1.0000x reference)
#include <cuda_runtime.h>
#include <cstdint>

// ---------------------------------------------------------------------------
// CoulombLayer, round 4:
//   out[a] = 0.5 * qi_c[a] * sum_{e: src=a} qj_c[dst] * chi(d)
// Edge kernel: 2 divergent mem ops per edge (gather qj, RED to src) — at the
// L1tex wavefront floor. This round trims correct_q (warp/molecule) and edge
// loop overhead (8 edges/thread).
// ---------------------------------------------------------------------------

#define MAX_ATOMS 500000

__device__ float g_qic[MAX_ATOMS];  // corrected charges scratch

// ---- Kernel A: charge correction, one warp per molecule, 8 mols/block ----
__global__ void __launch_bounds__(256) correct_q_kernel(
    const float* __restrict__ qi,
    const float* __restrict__ q_ref,
    const int*   __restrict__ Ncnt,
    int apm, int n_mol)
{
    const int wid = threadIdx.x >> 5;
    const int lid = threadIdx.x & 31;
    const int mol = blockIdx.x * 8 + wid;
    if (mol >= n_mol) return;

    const int base = mol * apm;
    const float* q = qi + base;

    float s = 0.f;
    for (int i = lid; i < apm; i += 32) s += q[i];

    #pragma unroll
    for (int off = 16; off > 0; off >>= 1)
        s += __shfl_xor_sync(0xFFFFFFFFu, s, off);

    // all lanes now hold the molecule sum
    const float corr = (s - q_ref[mol]) / (float)Ncnt[mol];

    for (int i = lid; i < apm; i += 32)
        g_qic[base + i] = q[i] - corr;
}

// ---- chi(r), cutoff=10 so x = 2r/10 = r/5 ----
__device__ __forceinline__ float chi_ij(float r)
{
    const float phi = rsqrtf(fmaf(r, r, 1.0f));
    const float x   = r * 0.2f;
    float f = 0.0f;
    if (x < 1.0f) {
        // 1 - 6x^5 + 15x^4 - 10x^3 = 1 - x^3*(6x^2 - 15x + 10)
        const float x3 = x * x * x;
        f = 1.0f - x3 * fmaf(x, fmaf(6.0f, x, -15.0f), 10.0f);
    }
    return f * phi + (1.0f - f) * __fdividef(1.0f, r);
}

// ---- Kernel B: edge pass, 8 edges per thread. Scatter qj*chi only. ----
__global__ void __launch_bounds__(256) edge_kernel(
    const float* __restrict__ dist,
    const int*   __restrict__ src,
    const int*   __restrict__ dst,
    float*       __restrict__ out,
    int n_oct)
{
    const int t = blockIdx.x * blockDim.x + threadIdx.x;
    if (t >= n_oct) return;

    const float4* d4  = reinterpret_cast<const float4*>(dist);
    const int4*   si4 = reinterpret_cast<const int4*>(src);
    const int4*   sj4 = reinterpret_cast<const int4*>(dst);

    const float4 da = d4[2 * t],      db = d4[2 * t + 1];
    const int4   sa = si4[2 * t],     sb = si4[2 * t + 1];
    const int4   ja = sj4[2 * t],     jb = sj4[2 * t + 1];

    // gathers (L2-resident 2MB table) — issue all 8 first for MLP
    const float qj0 = g_qic[ja.x];
    const float qj1 = g_qic[ja.y];
    const float qj2 = g_qic[ja.z];
    const float qj3 = g_qic[ja.w];
    const float qj4 = g_qic[jb.x];
    const float qj5 = g_qic[jb.y];
    const float qj6 = g_qic[jb.z];
    const float qj7 = g_qic[jb.w];

    atomicAdd(out + sa.x, qj0 * chi_ij(da.x));  // fire-and-forget -> RED
    atomicAdd(out + sa.y, qj1 * chi_ij(da.y));
    atomicAdd(out + sa.z, qj2 * chi_ij(da.z));
    atomicAdd(out + sa.w, qj3 * chi_ij(da.w));
    atomicAdd(out + sb.x, qj4 * chi_ij(db.x));
    atomicAdd(out + sb.y, qj5 * chi_ij(db.y));
    atomicAdd(out + sb.z, qj6 * chi_ij(db.z));
    atomicAdd(out + sb.w, qj7 * chi_ij(db.w));
}

// ---- tail edges (n_edges not divisible by 8), scalar ----
__global__ void edge_tail_kernel(
    const float* __restrict__ dist,
    const int*   __restrict__ src,
    const int*   __restrict__ dst,
    float*       __restrict__ out,
    int start, int n_edges)
{
    const int e = start + blockIdx.x * blockDim.x + threadIdx.x;
    if (e >= n_edges) return;
    atomicAdd(out + src[e], g_qic[dst[e]] * chi_ij(dist[e]));
}

// ---- Kernel C: finalize out[i] = 0.5 * qi_c[i] * acc[i] (in place) ----
__global__ void __launch_bounds__(256) finalize_kernel(
    float* __restrict__ out, int n_atoms)
{
    const int i = blockIdx.x * blockDim.x + threadIdx.x;
    if (i < n_atoms)
        out[i] = 0.5f * g_qic[i] * out[i];
}

extern "C" void kernel_launch(void* const* d_in, const int* in_sizes, int n_in,
                              void* d_out, int out_size)
{
    const float* qi        = (const float*)d_in[0];
    const float* edge_dist = (const float*)d_in[1];
    const int*   edge_idx  = (const int*)  d_in[2];
    const float* q_ref     = (const float*)d_in[3];
    const int*   Ncnt      = (const int*)  d_in[4];
    // d_in[5] = atom_mol_batch (implicit: atoms contiguous per mol)

    const int n_atoms = in_sizes[0];
    const int n_edges = in_sizes[1];
    const int n_mol   = in_sizes[3];
    const int apm     = n_atoms / n_mol;

    const int* src = edge_idx;            // row 0
    const int* dst = edge_idx + n_edges;  // row 1

    float* out = (float*)d_out;

    // zero accumulation target (harness poisons d_out)
    cudaMemsetAsync(out, 0, (size_t)out_size * sizeof(float), 0);

    // per-molecule correction: warp per molecule, 8 per block
    correct_q_kernel<<<(n_mol + 7) / 8, 256>>>(qi, q_ref, Ncnt, apm, n_mol);

    // edge pass: 8 edges per thread
    const int n_oct   = n_edges / 8;
    const int threads = 256;
    edge_kernel<<<(n_oct + threads - 1) / threads, threads>>>(
        edge_dist, src, dst, out, n_oct);

    const int done = n_oct * 8;
    if (done < n_edges) {
        const int rem = n_edges - done;
        edge_tail_kernel<<<(rem + 255) / 256, 256>>>(
            edge_dist, src, dst, out, done, n_edges);
    }

    // multiply by 0.5*qi_c in place
    finalize_kernel<<<(n_atoms + 255) / 256, 256>>>(out, n_atoms);
}

// round 6
// speedup vs baseline: 1.0487x; 1.0487x over previous
#include <cuda_runtime.h>
#include <cstdint>

// ---------------------------------------------------------------------------
// CoulombLayer, round 5 resubmit (infra failure, identical source):
//   out[a] = 0.5 * qi_c[a] * sum_{e: src=a} qj_c[dst] * chi(d)
// Edge kernel: 4 edges/thread (best measured config; 2 divergent mem ops per
// edge, at the L1tex wavefront floor). correct_q: warp/molecule + float2 loads.
// ---------------------------------------------------------------------------

#define MAX_ATOMS 500000

__device__ float g_qic[MAX_ATOMS];  // corrected charges scratch

// ---- Kernel A: charge correction, one warp per molecule, 8 mols/block ----
__global__ void __launch_bounds__(256) correct_q_kernel(
    const float* __restrict__ qi,
    const float* __restrict__ q_ref,
    const int*   __restrict__ Ncnt,
    int apm, int n_mol)
{
    const int wid = threadIdx.x >> 5;
    const int lid = threadIdx.x & 31;
    const int mol = blockIdx.x * 8 + wid;
    if (mol >= n_mol) return;

    const int base = mol * apm;

    float s = 0.f;
    if (((apm & 1) == 0) && ((base & 1) == 0)) {
        // vectorized path: apm/2 float2 elements
        const float2* q2 = reinterpret_cast<const float2*>(qi + base);
        const int n2 = apm >> 1;
        for (int i = lid; i < n2; i += 32) {
            const float2 v = q2[i];
            s += v.x + v.y;
        }
    } else {
        const float* q = qi + base;
        for (int i = lid; i < apm; i += 32) s += q[i];
    }

    #pragma unroll
    for (int off = 16; off > 0; off >>= 1)
        s += __shfl_xor_sync(0xFFFFFFFFu, s, off);

    // all lanes hold the molecule sum
    const float corr = (s - q_ref[mol]) / (float)Ncnt[mol];

    const float* q = qi + base;
    for (int i = lid; i < apm; i += 32)
        g_qic[base + i] = q[i] - corr;
}

// ---- chi(r), cutoff=10 so x = 2r/10 = r/5 ----
__device__ __forceinline__ float chi_ij(float r)
{
    const float phi = rsqrtf(fmaf(r, r, 1.0f));
    const float x   = r * 0.2f;
    float f = 0.0f;
    if (x < 1.0f) {
        // 1 - 6x^5 + 15x^4 - 10x^3 = 1 - x^3*(6x^2 - 15x + 10)
        const float x3 = x * x * x;
        f = 1.0f - x3 * fmaf(x, fmaf(6.0f, x, -15.0f), 10.0f);
    }
    return f * phi + (1.0f - f) * __fdividef(1.0f, r);
}

// ---- Kernel B: edge pass, 4 edges/thread. Scatter qj*chi only. ----
__global__ void __launch_bounds__(256) edge_kernel(
    const float* __restrict__ dist,
    const int*   __restrict__ src,
    const int*   __restrict__ dst,
    float*       __restrict__ out,
    int n_quads)
{
    const int t = blockIdx.x * blockDim.x + threadIdx.x;
    if (t >= n_quads) return;

    const float4 d  = reinterpret_cast<const float4*>(dist)[t];
    const int4   si = reinterpret_cast<const int4*>(src)[t];
    const int4   sj = reinterpret_cast<const int4*>(dst)[t];

    const float qj0 = g_qic[sj.x];
    const float qj1 = g_qic[sj.y];
    const float qj2 = g_qic[sj.z];
    const float qj3 = g_qic[sj.w];

    const float t0 = qj0 * chi_ij(d.x);
    const float t1 = qj1 * chi_ij(d.y);
    const float t2 = qj2 * chi_ij(d.z);
    const float t3 = qj3 * chi_ij(d.w);

    atomicAdd(out + si.x, t0);   // fire-and-forget -> RED
    atomicAdd(out + si.y, t1);
    atomicAdd(out + si.z, t2);
    atomicAdd(out + si.w, t3);
}

// ---- tail edges (n_edges not divisible by 4), scalar ----
__global__ void edge_tail_kernel(
    const float* __restrict__ dist,
    const int*   __restrict__ src,
    const int*   __restrict__ dst,
    float*       __restrict__ out,
    int start, int n_edges)
{
    const int e = start + blockIdx.x * blockDim.x + threadIdx.x;
    if (e >= n_edges) return;
    atomicAdd(out + src[e], g_qic[dst[e]] * chi_ij(dist[e]));
}

// ---- Kernel C: finalize out[i] = 0.5 * qi_c[i] * acc[i] (in place) ----
__global__ void __launch_bounds__(256) finalize_kernel(
    float* __restrict__ out, int n_atoms)
{
    const int i = blockIdx.x * blockDim.x + threadIdx.x;
    if (i < n_atoms)
        out[i] = 0.5f * g_qic[i] * out[i];
}

extern "C" void kernel_launch(void* const* d_in, const int* in_sizes, int n_in,
                              void* d_out, int out_size)
{
    const float* qi        = (const float*)d_in[0];
    const float* edge_dist = (const float*)d_in[1];
    const int*   edge_idx  = (const int*)  d_in[2];
    const float* q_ref     = (const float*)d_in[3];
    const int*   Ncnt      = (const int*)  d_in[4];
    // d_in[5] = atom_mol_batch (implicit: atoms contiguous per mol)

    const int n_atoms = in_sizes[0];
    const int n_edges = in_sizes[1];
    const int n_mol   = in_sizes[3];
    const int apm     = n_atoms / n_mol;

    const int* src = edge_idx;            // row 0
    const int* dst = edge_idx + n_edges;  // row 1

    float* out = (float*)d_out;

    // zero accumulation target (harness poisons d_out)
    cudaMemsetAsync(out, 0, (size_t)out_size * sizeof(float), 0);

    // per-molecule correction: warp per molecule, 8 per block
    correct_q_kernel<<<(n_mol + 7) / 8, 256>>>(qi, q_ref, Ncnt, apm, n_mol);

    // edge pass: 4 edges per thread
    const int n_quads = n_edges / 4;
    const int threads = 256;
    edge_kernel<<<(n_quads + threads - 1) / threads, threads>>>(
        edge_dist, src, dst, out, n_quads);

    const int done = n_quads * 4;
    if (done < n_edges) {
        const int rem = n_edges - done;
        edge_tail_kernel<<<(rem + 255) / 256, 256>>>(
            edge_dist, src, dst, out, done, n_edges);
    }

    // multiply by 0.5*qi_c in place
    finalize_kernel<<<(n_atoms + 255) / 256, 256>>>(out, n_atoms);
}

// round 7
// speedup vs baseline: 1.0521x; 1.0032x over previous
#include <cuda_runtime.h>
#include <cstdint>

// ---------------------------------------------------------------------------
// CoulombLayer, round 7:
//   out[a] = 0.5 * qi_c[a] * sum_{e: src=a} qj_c[dst] * chi(d)
// Edge kernel: 4 edges/thread, 2 divergent mem ops/edge — at the L1tex
// wavefront floor (measured ~129us vs ~114us theoretical).
// correct_q: warp/molecule, SINGLE global read (values cached in registers
// between the sum pass and the corrected write).
// ---------------------------------------------------------------------------

#define MAX_ATOMS 500000

__device__ float g_qic[MAX_ATOMS];  // corrected charges scratch

// ---- Kernel A: charge correction, one warp per molecule, 8 mols/block ----
// Assumes apm <= 128 (actual: 100): each lane owns at most 2 float2 pairs.
__global__ void __launch_bounds__(256) correct_q_kernel(
    const float* __restrict__ qi,
    const float* __restrict__ q_ref,
    const int*   __restrict__ Ncnt,
    int apm, int n_mol)
{
    const int wid = threadIdx.x >> 5;
    const int lid = threadIdx.x & 31;
    const int mol = blockIdx.x * 8 + wid;
    if (mol >= n_mol) return;

    const int base = mol * apm;

    if (((apm & 1) == 0) && ((base & 1) == 0) && (apm <= 128)) {
        // fast path: cache values in registers, one global read total
        const float2* q2 = reinterpret_cast<const float2*>(qi + base);
        const int n2 = apm >> 1;          // <= 64

        float2 v0 = make_float2(0.f, 0.f), v1 = make_float2(0.f, 0.f);
        const int i0 = lid;
        const int i1 = lid + 32;
        if (i0 < n2) v0 = __ldg(&q2[i0]);
        if (i1 < n2) v1 = __ldg(&q2[i1]);

        float s = v0.x + v0.y + v1.x + v1.y;
        #pragma unroll
        for (int off = 16; off > 0; off >>= 1)
            s += __shfl_xor_sync(0xFFFFFFFFu, s, off);

        const float corr = (s - q_ref[mol]) / (float)Ncnt[mol];

        float2* g2 = reinterpret_cast<float2*>(g_qic + base);
        if (i0 < n2) g2[i0] = make_float2(v0.x - corr, v0.y - corr);
        if (i1 < n2) g2[i1] = make_float2(v1.x - corr, v1.y - corr);
    } else {
        // generic fallback
        const float* q = qi + base;
        float s = 0.f;
        for (int i = lid; i < apm; i += 32) s += q[i];
        #pragma unroll
        for (int off = 16; off > 0; off >>= 1)
            s += __shfl_xor_sync(0xFFFFFFFFu, s, off);
        const float corr = (s - q_ref[mol]) / (float)Ncnt[mol];
        for (int i = lid; i < apm; i += 32)
            g_qic[base + i] = q[i] - corr;
    }
}

// ---- chi(r), cutoff=10 so x = 2r/10 = r/5 ----
__device__ __forceinline__ float chi_ij(float r)
{
    const float phi = rsqrtf(fmaf(r, r, 1.0f));
    const float x   = r * 0.2f;
    float f = 0.0f;
    if (x < 1.0f) {
        // 1 - 6x^5 + 15x^4 - 10x^3 = 1 - x^3*(6x^2 - 15x + 10)
        const float x3 = x * x * x;
        f = 1.0f - x3 * fmaf(x, fmaf(6.0f, x, -15.0f), 10.0f);
    }
    return f * phi + (1.0f - f) * __fdividef(1.0f, r);
}

// ---- Kernel B: edge pass, 4 edges/thread. Scatter qj*chi only. ----
__global__ void __launch_bounds__(256) edge_kernel(
    const float* __restrict__ dist,
    const int*   __restrict__ src,
    const int*   __restrict__ dst,
    float*       __restrict__ out,
    int n_quads)
{
    const int t = blockIdx.x * blockDim.x + threadIdx.x;
    if (t >= n_quads) return;

    const float4 d  = reinterpret_cast<const float4*>(dist)[t];
    const int4   si = reinterpret_cast<const int4*>(src)[t];
    const int4   sj = reinterpret_cast<const int4*>(dst)[t];

    const float qj0 = g_qic[sj.x];
    const float qj1 = g_qic[sj.y];
    const float qj2 = g_qic[sj.z];
    const float qj3 = g_qic[sj.w];

    const float t0 = qj0 * chi_ij(d.x);
    const float t1 = qj1 * chi_ij(d.y);
    const float t2 = qj2 * chi_ij(d.z);
    const float t3 = qj3 * chi_ij(d.w);

    atomicAdd(out + si.x, t0);   // fire-and-forget -> RED
    atomicAdd(out + si.y, t1);
    atomicAdd(out + si.z, t2);
    atomicAdd(out + si.w, t3);
}

// ---- tail edges (n_edges not divisible by 4), scalar ----
__global__ void edge_tail_kernel(
    const float* __restrict__ dist,
    const int*   __restrict__ src,
    const int*   __restrict__ dst,
    float*       __restrict__ out,
    int start, int n_edges)
{
    const int e = start + blockIdx.x * blockDim.x + threadIdx.x;
    if (e >= n_edges) return;
    atomicAdd(out + src[e], g_qic[dst[e]] * chi_ij(dist[e]));
}

// ---- Kernel C: finalize out[i] = 0.5 * qi_c[i] * acc[i] (in place) ----
__global__ void __launch_bounds__(256) finalize_kernel(
    float* __restrict__ out, int n_atoms)
{
    const int i = blockIdx.x * blockDim.x + threadIdx.x;
    if (i < n_atoms)
        out[i] = 0.5f * g_qic[i] * out[i];
}

extern "C" void kernel_launch(void* const* d_in, const int* in_sizes, int n_in,
                              void* d_out, int out_size)
{
    const float* qi        = (const float*)d_in[0];
    const float* edge_dist = (const float*)d_in[1];
    const int*   edge_idx  = (const int*)  d_in[2];
    const float* q_ref     = (const float*)d_in[3];
    const int*   Ncnt      = (const int*)  d_in[4];
    // d_in[5] = atom_mol_batch (implicit: atoms contiguous per mol)

    const int n_atoms = in_sizes[0];
    const int n_edges = in_sizes[1];
    const int n_mol   = in_sizes[3];
    const int apm     = n_atoms / n_mol;

    const int* src = edge_idx;            // row 0
    const int* dst = edge_idx + n_edges;  // row 1

    float* out = (float*)d_out;

    // zero accumulation target (harness poisons d_out)
    cudaMemsetAsync(out, 0, (size_t)out_size * sizeof(float), 0);

    // per-molecule correction: warp per molecule, 8 per block
    correct_q_kernel<<<(n_mol + 7) / 8, 256>>>(qi, q_ref, Ncnt, apm, n_mol);

    // edge pass: 4 edges per thread
    const int n_quads = n_edges / 4;
    const int threads = 256;
    edge_kernel<<<(n_quads + threads - 1) / threads, threads>>>(
        edge_dist, src, dst, out, n_quads);

    const int done = n_quads * 4;
    if (done < n_edges) {
        const int rem = n_edges - done;
        edge_tail_kernel<<<(rem + 255) / 256, 256>>>(
            edge_dist, src, dst, out, done, n_edges);
    }

    // multiply by 0.5*qi_c in place
    finalize_kernel<<<(n_atoms + 255) / 256, 256>>>(out, n_atoms);
}

// round 8
// speedup vs baseline: 1.0565x; 1.0042x over previous
#include <cuda_runtime.h>
#include <cstdint>

// ---------------------------------------------------------------------------
// CoulombLayer, round 8:
//   out[a] = 0.5 * qi_c[a] * sum_{e: src=a} qj_c[dst] * chi(d)
// Edge kernel: 4 edges/thread, 2 divergent mem ops/edge (L1tex wavefront
// floor, ~129us). This round: (1) RED into a self-rezeroing __device__
// accumulator, eliminating the memset node; (2) correct_q with 2 warps per
// molecule to double occupancy (was grid-limited at 53%).
// ---------------------------------------------------------------------------

#define MAX_ATOMS 500000

__device__ float g_qic[MAX_ATOMS];  // corrected charges scratch
__device__ float g_acc[MAX_ATOMS];  // RED accumulator; zero at entry of every
                                    // call (zero-init + finalize re-zeroes)

// ---- Kernel A: charge correction, TWO warps per molecule, 4 mols/block ----
__global__ void __launch_bounds__(256) correct_q_kernel(
    const float* __restrict__ qi,
    const float* __restrict__ q_ref,
    const int*   __restrict__ Ncnt,
    int apm, int n_mol)
{
    const int wid  = threadIdx.x >> 5;     // 0..7
    const int lid  = threadIdx.x & 31;
    const int mslot = wid >> 1;            // 0..3  molecule slot in block
    const int half  = wid & 1;             // which half of the molecule
    const int mol  = blockIdx.x * 4 + mslot;

    __shared__ float s_part[4][2];
    __shared__ float s_corr[4];

    float s = 0.f;
    int base = 0;

    if (mol < n_mol) {
        base = mol * apm;
        if (((apm & 1) == 0) && ((base & 1) == 0)) {
            const float2* q2 = reinterpret_cast<const float2*>(qi + base);
            const int n2    = apm >> 1;
            const int chunk = (n2 + 1) >> 1;
            const int lo = half * chunk;
            const int hi = min(n2, lo + chunk);
            for (int i = lo + lid; i < hi; i += 32) {
                const float2 v = __ldg(&q2[i]);
                s += v.x + v.y;
            }
        } else {
            const float* q = qi + base;
            const int chunk = (apm + 1) >> 1;
            const int lo = half * chunk;
            const int hi = min(apm, lo + chunk);
            for (int i = lo + lid; i < hi; i += 32) s += q[i];
        }
    }

    #pragma unroll
    for (int off = 16; off > 0; off >>= 1)
        s += __shfl_xor_sync(0xFFFFFFFFu, s, off);

    if (lid == 0) s_part[mslot][half] = s;
    __syncthreads();

    if (mol < n_mol && half == 0 && lid == 0) {
        const float tot = s_part[mslot][0] + s_part[mslot][1];
        s_corr[mslot] = (tot - q_ref[mol]) / (float)Ncnt[mol];
    }
    __syncthreads();

    if (mol >= n_mol) return;
    const float corr = s_corr[mslot];

    // write corrected charges: each warp writes its half (coalesced)
    const float* q = qi + base;
    const int chunk = (apm + 1) >> 1;
    const int lo = half * chunk;
    const int hi = min(apm, lo + chunk);
    for (int i = lo + lid; i < hi; i += 32)
        g_qic[base + i] = q[i] - corr;
}

// ---- chi(r), cutoff=10 so x = 2r/10 = r/5 ----
__device__ __forceinline__ float chi_ij(float r)
{
    const float phi = rsqrtf(fmaf(r, r, 1.0f));
    const float x   = r * 0.2f;
    float f = 0.0f;
    if (x < 1.0f) {
        // 1 - 6x^5 + 15x^4 - 10x^3 = 1 - x^3*(6x^2 - 15x + 10)
        const float x3 = x * x * x;
        f = 1.0f - x3 * fmaf(x, fmaf(6.0f, x, -15.0f), 10.0f);
    }
    return f * phi + (1.0f - f) * __fdividef(1.0f, r);
}

// ---- Kernel B: edge pass, 4 edges/thread. RED qj*chi into g_acc. ----
__global__ void __launch_bounds__(256) edge_kernel(
    const float* __restrict__ dist,
    const int*   __restrict__ src,
    const int*   __restrict__ dst,
    int n_quads)
{
    const int t = blockIdx.x * blockDim.x + threadIdx.x;
    if (t >= n_quads) return;

    const float4 d  = reinterpret_cast<const float4*>(dist)[t];
    const int4   si = reinterpret_cast<const int4*>(src)[t];
    const int4   sj = reinterpret_cast<const int4*>(dst)[t];

    const float qj0 = g_qic[sj.x];
    const float qj1 = g_qic[sj.y];
    const float qj2 = g_qic[sj.z];
    const float qj3 = g_qic[sj.w];

    const float t0 = qj0 * chi_ij(d.x);
    const float t1 = qj1 * chi_ij(d.y);
    const float t2 = qj2 * chi_ij(d.z);
    const float t3 = qj3 * chi_ij(d.w);

    atomicAdd(g_acc + si.x, t0);   // fire-and-forget -> RED
    atomicAdd(g_acc + si.y, t1);
    atomicAdd(g_acc + si.z, t2);
    atomicAdd(g_acc + si.w, t3);
}

// ---- tail edges (n_edges not divisible by 4), scalar ----
__global__ void edge_tail_kernel(
    const float* __restrict__ dist,
    const int*   __restrict__ src,
    const int*   __restrict__ dst,
    int start, int n_edges)
{
    const int e = start + blockIdx.x * blockDim.x + threadIdx.x;
    if (e >= n_edges) return;
    atomicAdd(g_acc + src[e], g_qic[dst[e]] * chi_ij(dist[e]));
}

// ---- Kernel C: finalize out[i] = 0.5*qi_c[i]*acc[i]; re-zero accumulator ----
__global__ void __launch_bounds__(256) finalize_kernel(
    float* __restrict__ out, int n_atoms)
{
    const int i = blockIdx.x * blockDim.x + threadIdx.x;
    if (i < n_atoms) {
        out[i] = 0.5f * g_qic[i] * g_acc[i];
        g_acc[i] = 0.0f;     // restore zero-invariant for next call/replay
    }
}

extern "C" void kernel_launch(void* const* d_in, const int* in_sizes, int n_in,
                              void* d_out, int out_size)
{
    const float* qi        = (const float*)d_in[0];
    const float* edge_dist = (const float*)d_in[1];
    const int*   edge_idx  = (const int*)  d_in[2];
    const float* q_ref     = (const float*)d_in[3];
    const int*   Ncnt      = (const int*)  d_in[4];
    // d_in[5] = atom_mol_batch (implicit: atoms contiguous per mol)

    const int n_atoms = in_sizes[0];
    const int n_edges = in_sizes[1];
    const int n_mol   = in_sizes[3];
    const int apm     = n_atoms / n_mol;

    const int* src = edge_idx;            // row 0
    const int* dst = edge_idx + n_edges;  // row 1

    float* out = (float*)d_out;

    // per-molecule correction: 2 warps per molecule, 4 mols per block
    correct_q_kernel<<<(n_mol + 3) / 4, 256>>>(qi, q_ref, Ncnt, apm, n_mol);

    // edge pass: 4 edges per thread, RED into g_acc (zero at entry)
    const int n_quads = n_edges / 4;
    const int threads = 256;
    edge_kernel<<<(n_quads + threads - 1) / threads, threads>>>(
        edge_dist, src, dst, n_quads);

    const int done = n_quads * 4;
    if (done < n_edges) {
        const int rem = n_edges - done;
        edge_tail_kernel<<<(rem + 255) / 256, 256>>>(
            edge_dist, src, dst, done, n_edges);
    }

    // out = 0.5 * qi_c * acc ; g_acc re-zeroed for the next invocation
    finalize_kernel<<<(n_atoms + 255) / 256, 256>>>(out, n_atoms);
}